// round 13
// baseline (speedup 1.0000x reference)
#include <cuda_runtime.h>
#include <cstdint>

// Problem constants
#define N_ENS  4
#define N_IN   16384
#define N_OUT  4096
#define CIN    16
#define COUT   16
#define KS     1024                  // K-slab (floats) staged in SMEM per buffer
#define THREADS 256                  // 8 warps x 4 rows = 32 rows/block
#define ROWTILES (N_OUT / 32)        // 128 row tiles
#define GRID_MAIN (ROWTILES * N_ENS * 2)   // 1024 items: (t, n, k-half)
#define KHALF (N_IN / 2)             // 8192 k per item
#define SLABS_ITEM (KHALF / KS)      // 8 slabs per item
#define NBLK_ITEM (SLABS_ITEM * 4)   // 32 A-pipeline blocks (256 k each)

// Scratch: xw planes [n][g2][i] as float2 (pair over g). 4 MB, 16B-aligned.
__device__ float4 g_xwT4[(N_ENS * 8 * N_IN) / 2];
// Partial outputs: plane p = n*2 + h, [p][row][g2] float2. 2 MB.
__device__ float2 g_part[8 * N_OUT * 8];

union F2U { float2 f; unsigned long long u; };

__device__ __forceinline__ float2 ffma2(float2 a, float2 b, float2 c) {
    F2U A, B, C, D;
    A.f = a; B.f = b; C.f = c;
    asm("fma.rn.f32x2 %0, %1, %2, %3;"
        : "=l"(D.u) : "l"(A.u), "l"(B.u), "l"(C.u));
    return D.f;
}

__device__ __forceinline__ uint32_t smem_u32(const void* p) {
    uint32_t a;
    asm("{ .reg .u64 t; cvta.to.shared.u64 t, %1; cvt.u32.u64 %0, t; }"
        : "=r"(a) : "l"(p));
    return a;
}

__device__ __forceinline__ void cp_async16(uint32_t saddr, const void* gptr) {
    asm volatile("cp.async.cg.shared.global [%0], [%1], 16;"
                 :: "r"(saddr), "l"(gptr));
}
__device__ __forceinline__ void cp_commit() {
    asm volatile("cp.async.commit_group;");
}

// ---------------------------------------------------------------------------
// Kernel 0: xw[n][i][g] = 0.25 * sum_f x[i][f] * W[n][f][g], plane-major
// float2: g_xwT[(n*8+g2)*N_IN + i].
// ---------------------------------------------------------------------------
__global__ void precompute_xw(const float* __restrict__ x,
                              const float* __restrict__ Ws) {
    __shared__ float sW[CIN * COUT];
    const int n = blockIdx.y;
    sW[threadIdx.x] = Ws[n * (CIN * COUT) + threadIdx.x];
    __syncthreads();

    const int i = blockIdx.x * 256 + threadIdx.x;

    float xf[16];
    const float4* xv = reinterpret_cast<const float4*>(x + (size_t)i * CIN);
#pragma unroll
    for (int q = 0; q < 4; ++q)
        reinterpret_cast<float4*>(xf)[q] = xv[q];

    float y[16];
#pragma unroll
    for (int g = 0; g < 16; ++g) y[g] = 0.f;
#pragma unroll
    for (int f = 0; f < 16; ++f)
#pragma unroll
        for (int g = 0; g < 16; ++g)
            y[g] += xf[f] * sW[f * 16 + g];

    float2* xwT = reinterpret_cast<float2*>(g_xwT4);
#pragma unroll
    for (int g2 = 0; g2 < 8; ++g2)
        xwT[(size_t)(n * 8 + g2) * N_IN + i] =
            make_float2(0.25f * y[2 * g2], 0.25f * y[2 * g2 + 1]);
}

// ---------------------------------------------------------------------------
// Main kernel. Work item = (row-tile t, ensemble n, K-half h); grid 1024.
// 8 warps x 4 rows/warp = 32 rows/item; 8 K-slabs of 1024 per item.
// Mainloop identical to the R12 kernel: lane L owns k = {2L,2L+1};
// A LDG.64 coalesced, 4-stage register pipeline (stage-3 loads interleaved
// per ts-iter); xw slabs cp.async double-buffered, one __syncthreads/slab.
// Each block writes its own partial plane slice -> deterministic, no atomics.
// ---------------------------------------------------------------------------
extern __shared__ float2 s_xw[];   // 2 buffers x 8*KS float2 = 128 KB

__global__ __launch_bounds__(THREADS, 1)
void mfgl_main(const float* __restrict__ A) {
    const int bid  = blockIdx.x;
    const int t    = bid >> 3;            // row tile 0..127
    const int n    = (bid >> 1) & 3;      // ensemble 0..3
    const int h    = bid & 1;             // K-half 0..1
    const int tid  = threadIdx.x;
    const int lane = tid & 31;
    const int wid  = tid >> 5;
    const int row0 = t * 32 + wid * 4;
    const int kbase = h * KHALF;

    const float2* __restrict__ xwT =
        reinterpret_cast<const float2*>(g_xwT4) + (size_t)n * 8 * N_IN;
    const uint32_t sbase = smem_u32(s_xw);

    float2 acc[4][8];
#pragma unroll
    for (int r = 0; r < 4; ++r)
#pragma unroll
        for (int g = 0; g < 8; ++g)
            acc[r][g] = make_float2(0.f, 0.f);

    // A base of pipeline block bl in [0, 32): slab bl>>2, 256-k chunk bl&3.
    auto a_base = [&](int bl) -> const float2* {
        const int k0 = kbase + (bl >> 2) * KS + (bl & 3) * 256;
        return reinterpret_cast<const float2*>(
            A + ((size_t)(n * N_OUT + row0)) * N_IN + k0) + lane;
    };

    // cp.async one xw slab (this item's ensemble) into buffer BUF.
    // 64 KB = 4096 x 16B chunks; 512 chunks per g2-plane.
#define PREFETCH_XW(S, BUF)                                                 \
    do {                                                                    \
        const int _k0 = kbase + (S) * KS;                                   \
        const uint32_t _dst = sbase + (BUF) * 65536u + (uint32_t)tid * 16u; \
        _Pragma("unroll")                                                   \
        for (int _i = 0; _i < 16; ++_i) {                                   \
            const int _c  = tid + _i * THREADS;                             \
            const int _g2 = _c >> 9;                                        \
            const int _kk = (_c & 511) << 1;                                \
            cp_async16(_dst + (uint32_t)_i * (THREADS * 16u),               \
                       xwT + (size_t)_g2 * N_IN + _k0 + _kk);               \
        }                                                                   \
        cp_commit();                                                        \
    } while (0)

    PREFETCH_XW(0, 0);

    // Prime 4-stage A register pipeline with blocks 0, 1, 2.
    float2 cur[4][4], nx1[4][4], nx2[4][4];
    {
        const float2* p0 = a_base(0);
        const float2* p1 = a_base(1);
        const float2* p2 = a_base(2);
#pragma unroll
        for (int r = 0; r < 4; ++r)
#pragma unroll
            for (int ts = 0; ts < 4; ++ts) {
                cur[r][ts] = p0[(size_t)r * (N_IN / 2) + ts * 32];
                nx1[r][ts] = p1[(size_t)r * (N_IN / 2) + ts * 32];
                nx2[r][ts] = p2[(size_t)r * (N_IN / 2) + ts * 32];
            }
    }

    for (int s = 0; s < SLABS_ITEM; ++s) {
        asm volatile("cp.async.wait_group 0;");  // slab s data (mine) done
        __syncthreads();                          // all done + WAR safe
        if (s + 1 < SLABS_ITEM)
            PREFETCH_XW(s + 1, (s + 1) & 1);      // overlaps compute below

        const float2* __restrict__ sx = s_xw + (s & 1) * (8 * KS);

#pragma unroll
        for (int tb = 0; tb < 4; ++tb) {
            int bl3 = s * 4 + tb + 3;
            if (bl3 >= NBLK_ITEM) bl3 -= NBLK_ITEM;  // dead load, in-bounds
            const float2* __restrict__ pb3 = a_base(bl3);
            float2 nx3[4][4];

#pragma unroll
            for (int ts = 0; ts < 4; ++ts) {
                // issue 4 LDG.64 (row `ts` of block bl+3), smooth stream
#pragma unroll
                for (int q = 0; q < 4; ++q)
                    nx3[ts][q] = pb3[(size_t)ts * (N_IN / 2) + q * 32];

                // compute big-iter ts of current block
                const int off = (tb * 4 + ts) * 64 + 2 * lane;  // float2 idx
                const float2 a0 = cur[0][ts];
                const float2 a1 = cur[1][ts];
                const float2 a2 = cur[2][ts];
                const float2 a3 = cur[3][ts];
                const float2 p0x = make_float2(a0.x, a0.x);
                const float2 p0y = make_float2(a0.y, a0.y);
                const float2 p1x = make_float2(a1.x, a1.x);
                const float2 p1y = make_float2(a1.y, a1.y);
                const float2 p2x = make_float2(a2.x, a2.x);
                const float2 p2y = make_float2(a2.y, a2.y);
                const float2 p3x = make_float2(a3.x, a3.x);
                const float2 p3y = make_float2(a3.y, a3.y);
#pragma unroll
                for (int g2 = 0; g2 < 8; ++g2) {
                    const float4 wv = *reinterpret_cast<const float4*>(
                        sx + (size_t)g2 * KS + off);
                    const float2 wk0 = make_float2(wv.x, wv.y);
                    const float2 wk1 = make_float2(wv.z, wv.w);
                    acc[0][g2] = ffma2(p0x, wk0, acc[0][g2]);
                    acc[0][g2] = ffma2(p0y, wk1, acc[0][g2]);
                    acc[1][g2] = ffma2(p1x, wk0, acc[1][g2]);
                    acc[1][g2] = ffma2(p1y, wk1, acc[1][g2]);
                    acc[2][g2] = ffma2(p2x, wk0, acc[2][g2]);
                    acc[2][g2] = ffma2(p2y, wk1, acc[2][g2]);
                    acc[3][g2] = ffma2(p3x, wk0, acc[3][g2]);
                    acc[3][g2] = ffma2(p3y, wk1, acc[3][g2]);
                }
            }

            // rotate pipeline (register renames under full unroll)
#pragma unroll
            for (int r = 0; r < 4; ++r)
#pragma unroll
                for (int ts = 0; ts < 4; ++ts) {
                    cur[r][ts] = nx1[r][ts];
                    nx1[r][ts] = nx2[r][ts];
                    nx2[r][ts] = nx3[r][ts];
                }
        }
    }

    // Warp-level butterfly reduction across the 32-lane K split.
#pragma unroll
    for (int r = 0; r < 4; ++r)
#pragma unroll
        for (int g = 0; g < 8; ++g) {
            float xx = acc[r][g].x;
            float yy = acc[r][g].y;
#pragma unroll
            for (int off = 16; off > 0; off >>= 1) {
                xx += __shfl_xor_sync(0xffffffffu, xx, off);
                yy += __shfl_xor_sync(0xffffffffu, yy, off);
            }
            acc[r][g] = make_float2(xx, yy);
        }

    if (lane == 0) {
        float2* part = g_part + (size_t)(n * 2 + h) * N_OUT * 8;
#pragma unroll
        for (int r = 0; r < 4; ++r)
#pragma unroll
            for (int g2 = 0; g2 < 8; ++g2)
                part[(size_t)(row0 + r) * 8 + g2] = acc[r][g2];
    }
}

// ---------------------------------------------------------------------------
// Reduce: out[o][g] = sum over 8 partial planes + mean bias. ~3 us.
// ---------------------------------------------------------------------------
__global__ void reduce_out(const float* __restrict__ bs,
                           float* __restrict__ out) {
    const int e = blockIdx.x * 256 + threadIdx.x;   // [0, 4096*8)
    const int g2 = e & 7;
    const int g = 2 * g2;

    float xx = 0.25f * (bs[g]     + bs[16 + g]     + bs[32 + g]     + bs[48 + g]);
    float yy = 0.25f * (bs[g + 1] + bs[16 + g + 1] + bs[32 + g + 1] + bs[48 + g + 1]);
#pragma unroll
    for (int p = 0; p < 8; ++p) {
        const float2 v = g_part[(size_t)p * N_OUT * 8 + e];
        xx += v.x;
        yy += v.y;
    }
    reinterpret_cast<float2*>(out)[e] = make_float2(xx, yy);
}

// ---------------------------------------------------------------------------
// Launch: inputs in metadata order: x, As, Ws, bs. Output fp32 [4096,16].
// ---------------------------------------------------------------------------
extern "C" void kernel_launch(void* const* d_in, const int* in_sizes, int n_in,
                              void* d_out, int out_size) {
    const float* x  = (const float*)d_in[0];
    const float* As = (const float*)d_in[1];
    const float* Ws = (const float*)d_in[2];
    const float* bs = (const float*)d_in[3];
    float* out = (float*)d_out;

    precompute_xw<<<dim3(N_IN / 256, N_ENS), 256>>>(x, Ws);

    const int smem_bytes = 2 * 8 * KS * (int)sizeof(float2);  // 131072
    cudaFuncSetAttribute(mfgl_main,
                         cudaFuncAttributeMaxDynamicSharedMemorySize,
                         smem_bytes);
    mfgl_main<<<GRID_MAIN, THREADS, smem_bytes>>>(As);

    reduce_out<<<(N_OUT * 8) / 256, 256>>>(bs, out);
}

// round 14
// speedup vs baseline: 1.0503x; 1.0503x over previous
#include <cuda_runtime.h>
#include <cstdint>

// Problem constants
#define N_ENS  4
#define N_IN   16384
#define N_OUT  4096
#define CIN    16
#define COUT   16
#define KS     1024                  // K-slab (floats) staged in SMEM per buffer
#define THREADS 256                  // 8 warps x 4 rows = 32 rows/item
#define KHALF (N_IN / 2)             // 8192 k per item
#define SLABS_ITEM (KHALF / KS)      // 8 slabs per item
#define N_ITEMS 1024                 // (row-tile t, ensemble n, K-half h)
#define GRID_P 148                   // persistent: one CTA per SM

// Scratch: xw planes [n][g2][i] as float2 (pair over g). 4 MB, 16B-aligned.
__device__ float4 g_xwT4[(N_ENS * 8 * N_IN) / 2];
// Partial outputs: plane p = n*2 + h, [p][row][g2] float2. 2 MB.
__device__ float2 g_part[8 * N_OUT * 8];

union F2U { float2 f; unsigned long long u; };

__device__ __forceinline__ float2 ffma2(float2 a, float2 b, float2 c) {
    F2U A, B, C, D;
    A.f = a; B.f = b; C.f = c;
    asm("fma.rn.f32x2 %0, %1, %2, %3;"
        : "=l"(D.u) : "l"(A.u), "l"(B.u), "l"(C.u));
    return D.f;
}

__device__ __forceinline__ uint32_t smem_u32(const void* p) {
    uint32_t a;
    asm("{ .reg .u64 t; cvta.to.shared.u64 t, %1; cvt.u32.u64 %0, t; }"
        : "=r"(a) : "l"(p));
    return a;
}

__device__ __forceinline__ void cp_async16(uint32_t saddr, const void* gptr) {
    asm volatile("cp.async.cg.shared.global [%0], [%1], 16;"
                 :: "r"(saddr), "l"(gptr));
}
__device__ __forceinline__ void cp_commit() {
    asm volatile("cp.async.commit_group;");
}

// ---------------------------------------------------------------------------
// Kernel 0: xw[n][i][g] = 0.25 * sum_f x[i][f] * W[n][f][g], plane-major
// float2: g_xwT[(n*8+g2)*N_IN + i].
// ---------------------------------------------------------------------------
__global__ void precompute_xw(const float* __restrict__ x,
                              const float* __restrict__ Ws) {
    __shared__ float sW[CIN * COUT];
    const int n = blockIdx.y;
    sW[threadIdx.x] = Ws[n * (CIN * COUT) + threadIdx.x];
    __syncthreads();

    const int i = blockIdx.x * 256 + threadIdx.x;

    float xf[16];
    const float4* xv = reinterpret_cast<const float4*>(x + (size_t)i * CIN);
#pragma unroll
    for (int q = 0; q < 4; ++q)
        reinterpret_cast<float4*>(xf)[q] = xv[q];

    float y[16];
#pragma unroll
    for (int g = 0; g < 16; ++g) y[g] = 0.f;
#pragma unroll
    for (int f = 0; f < 16; ++f)
#pragma unroll
        for (int g = 0; g < 16; ++g)
            y[g] += xf[f] * sW[f * 16 + g];

    float2* xwT = reinterpret_cast<float2*>(g_xwT4);
#pragma unroll
    for (int g2 = 0; g2 < 8; ++g2)
        xwT[(size_t)(n * 8 + g2) * N_IN + i] =
            make_float2(0.25f * y[2 * g2], 0.25f * y[2 * g2 + 1]);
}

// ---------------------------------------------------------------------------
// Persistent main kernel. 148 CTAs; CTA c owns items {c, c+148, ...} (<=7).
// Item = (t, n, h): 32 rows (8 warps x 4), one ensemble, one 8192-k half.
// Slab stream u = slot*8 + s and A-block stream seq = u*4 + tb are flat and
// continuous across items: the cp.async double buffer and the 4-stage A
// register pipeline never drain at item boundaries. Accumulators reset at
// each item's first slab; epilogue writes that item's g_part slice.
// ---------------------------------------------------------------------------
extern __shared__ float2 s_xw[];   // 2 buffers x 8*KS float2 = 128 KB

__global__ __launch_bounds__(THREADS, 1)
void mfgl_main(const float* __restrict__ A) {
    const int cta  = blockIdx.x;
    const int tid  = threadIdx.x;
    const int lane = tid & 31;
    const int wid  = tid >> 5;

    const int nslots = (N_ITEMS - cta + GRID_P - 1) / GRID_P;  // 6 or 7
    const int U = nslots * SLABS_ITEM;                          // slabs total

    const float2* __restrict__ xwT0 = reinterpret_cast<const float2*>(g_xwT4);
    const uint32_t sbase = smem_u32(s_xw);

    // item id for slot (clamped to a valid item for dead pipeline loads)
    auto item_of = [&](int slot) -> int {
        int it = cta + slot * GRID_P;
        return (it < N_ITEMS) ? it : cta;
    };

    // A pointer for global A-block seq (128 blocks/item of 64 k... here:
    // seq in [0, U*4); block bl = seq & 31 within item slot = seq >> 5).
    auto a_ptr = [&](int seq) -> const float2* {
        const int slot = seq >> 5;
        const int bl   = seq & 31;
        const int it   = item_of(slot);
        const int t    = it >> 3;
        const int n    = (it >> 1) & 3;
        const int h    = it & 1;
        const int row0 = t * 32 + wid * 4;
        const int k0   = h * KHALF + (bl >> 2) * KS + (bl & 3) * 256;
        return reinterpret_cast<const float2*>(
            A + ((size_t)(n * N_OUT + row0)) * N_IN + k0) + lane;
    };

    // cp.async slab stream element UU into buffer UU&1.
#define PREFETCH_XW_SEQ(UU)                                                 \
    do {                                                                    \
        const int _slot = (UU) >> 3;                                        \
        const int _s    = (UU) & 7;                                         \
        const int _it   = item_of(_slot);                                   \
        const int _n    = (_it >> 1) & 3;                                   \
        const int _h    = _it & 1;                                          \
        const float2* __restrict__ _xw = xwT0 + (size_t)_n * 8 * N_IN;      \
        const int _k0 = _h * KHALF + _s * KS;                               \
        const uint32_t _dst = sbase + ((UU) & 1) * 65536u                   \
                              + (uint32_t)tid * 16u;                        \
        _Pragma("unroll")                                                   \
        for (int _i = 0; _i < 16; ++_i) {                                   \
            const int _c  = tid + _i * THREADS;                             \
            const int _g2 = _c >> 9;            /* 512 chunks per plane */  \
            const int _kk = (_c & 511) << 1;                                \
            cp_async16(_dst + (uint32_t)_i * (THREADS * 16u),               \
                       _xw + (size_t)_g2 * N_IN + _k0 + _kk);               \
        }                                                                   \
        cp_commit();                                                        \
    } while (0)

    PREFETCH_XW_SEQ(0);

    // Prime 4-stage A register pipeline with seq 0, 1, 2.
    float2 cur[4][4], nx1[4][4], nx2[4][4];
    {
        const float2* p0 = a_ptr(0);
        const float2* p1 = a_ptr(1);
        const float2* p2 = a_ptr(2);
#pragma unroll
        for (int r = 0; r < 4; ++r)
#pragma unroll
            for (int ts = 0; ts < 4; ++ts) {
                cur[r][ts] = p0[(size_t)r * (N_IN / 2) + ts * 32];
                nx1[r][ts] = p1[(size_t)r * (N_IN / 2) + ts * 32];
                nx2[r][ts] = p2[(size_t)r * (N_IN / 2) + ts * 32];
            }
    }

    float2 acc[4][8];

    for (int u = 0; u < U; ++u) {
        const int s = u & 7;

        if (s == 0) {
            // new item: reset accumulators
#pragma unroll
            for (int r = 0; r < 4; ++r)
#pragma unroll
                for (int g = 0; g < 8; ++g)
                    acc[r][g] = make_float2(0.f, 0.f);
        }

        asm volatile("cp.async.wait_group 0;");  // slab u data (mine) done
        __syncthreads();                          // all done + WAR safe
        if (u + 1 < U)
            PREFETCH_XW_SEQ(u + 1);               // overlaps compute below

        const float2* __restrict__ sx = s_xw + (u & 1) * (8 * KS);

#pragma unroll
        for (int tb = 0; tb < 4; ++tb) {
            const int seq3 = u * 4 + tb + 3;      // a_ptr clamps overflow
            const float2* __restrict__ pb3 = a_ptr(seq3);
            float2 nx3[4][4];

#pragma unroll
            for (int ts = 0; ts < 4; ++ts) {
                // issue 4 LDG.64 (row `ts` of block seq+3), smooth stream
#pragma unroll
                for (int q = 0; q < 4; ++q)
                    nx3[ts][q] = pb3[(size_t)ts * (N_IN / 2) + q * 32];

                // compute big-iter ts of current block
                const int off = (tb * 4 + ts) * 64 + 2 * lane;  // float2 idx
                const float2 a0 = cur[0][ts];
                const float2 a1 = cur[1][ts];
                const float2 a2 = cur[2][ts];
                const float2 a3 = cur[3][ts];
                const float2 p0x = make_float2(a0.x, a0.x);
                const float2 p0y = make_float2(a0.y, a0.y);
                const float2 p1x = make_float2(a1.x, a1.x);
                const float2 p1y = make_float2(a1.y, a1.y);
                const float2 p2x = make_float2(a2.x, a2.x);
                const float2 p2y = make_float2(a2.y, a2.y);
                const float2 p3x = make_float2(a3.x, a3.x);
                const float2 p3y = make_float2(a3.y, a3.y);
#pragma unroll
                for (int g2 = 0; g2 < 8; ++g2) {
                    const float4 wv = *reinterpret_cast<const float4*>(
                        sx + (size_t)g2 * KS + off);
                    const float2 wk0 = make_float2(wv.x, wv.y);
                    const float2 wk1 = make_float2(wv.z, wv.w);
                    acc[0][g2] = ffma2(p0x, wk0, acc[0][g2]);
                    acc[0][g2] = ffma2(p0y, wk1, acc[0][g2]);
                    acc[1][g2] = ffma2(p1x, wk0, acc[1][g2]);
                    acc[1][g2] = ffma2(p1y, wk1, acc[1][g2]);
                    acc[2][g2] = ffma2(p2x, wk0, acc[2][g2]);
                    acc[2][g2] = ffma2(p2y, wk1, acc[2][g2]);
                    acc[3][g2] = ffma2(p3x, wk0, acc[3][g2]);
                    acc[3][g2] = ffma2(p3y, wk1, acc[3][g2]);
                }
            }

            // rotate pipeline (register renames under full unroll)
#pragma unroll
            for (int r = 0; r < 4; ++r)
#pragma unroll
                for (int ts = 0; ts < 4; ++ts) {
                    cur[r][ts] = nx1[r][ts];
                    nx1[r][ts] = nx2[r][ts];
                    nx2[r][ts] = nx3[r][ts];
                }
        }

        if (s == 7) {
            // item complete: butterfly-reduce K split and write partials.
            const int it   = item_of(u >> 3);
            const int t    = it >> 3;
            const int n    = (it >> 1) & 3;
            const int h    = it & 1;
            const int row0 = t * 32 + wid * 4;

#pragma unroll
            for (int r = 0; r < 4; ++r)
#pragma unroll
                for (int g = 0; g < 8; ++g) {
                    float xx = acc[r][g].x;
                    float yy = acc[r][g].y;
#pragma unroll
                    for (int off = 16; off > 0; off >>= 1) {
                        xx += __shfl_xor_sync(0xffffffffu, xx, off);
                        yy += __shfl_xor_sync(0xffffffffu, yy, off);
                    }
                    acc[r][g] = make_float2(xx, yy);
                }

            if (lane == 0) {
                float2* part = g_part + (size_t)(n * 2 + h) * N_OUT * 8;
#pragma unroll
                for (int r = 0; r < 4; ++r)
#pragma unroll
                    for (int g2 = 0; g2 < 8; ++g2)
                        part[(size_t)(row0 + r) * 8 + g2] = acc[r][g2];
            }
        }
    }
}

// ---------------------------------------------------------------------------
// Reduce: out[o][g] = sum over 8 partial planes + mean bias. ~3 us.
// ---------------------------------------------------------------------------
__global__ void reduce_out(const float* __restrict__ bs,
                           float* __restrict__ out) {
    const int e = blockIdx.x * 256 + threadIdx.x;   // [0, 4096*8)
    const int g2 = e & 7;
    const int g = 2 * g2;

    float xx = 0.25f * (bs[g]     + bs[16 + g]     + bs[32 + g]     + bs[48 + g]);
    float yy = 0.25f * (bs[g + 1] + bs[16 + g + 1] + bs[32 + g + 1] + bs[48 + g + 1]);
#pragma unroll
    for (int p = 0; p < 8; ++p) {
        const float2 v = g_part[(size_t)p * N_OUT * 8 + e];
        xx += v.x;
        yy += v.y;
    }
    reinterpret_cast<float2*>(out)[e] = make_float2(xx, yy);
}

// ---------------------------------------------------------------------------
// Launch: inputs in metadata order: x, As, Ws, bs. Output fp32 [4096,16].
// ---------------------------------------------------------------------------
extern "C" void kernel_launch(void* const* d_in, const int* in_sizes, int n_in,
                              void* d_out, int out_size) {
    const float* x  = (const float*)d_in[0];
    const float* As = (const float*)d_in[1];
    const float* Ws = (const float*)d_in[2];
    const float* bs = (const float*)d_in[3];
    float* out = (float*)d_out;

    precompute_xw<<<dim3(N_IN / 256, N_ENS), 256>>>(x, Ws);

    const int smem_bytes = 2 * 8 * KS * (int)sizeof(float2);  // 131072
    cudaFuncSetAttribute(mfgl_main,
                         cudaFuncAttributeMaxDynamicSharedMemorySize,
                         smem_bytes);
    mfgl_main<<<GRID_P, THREADS, smem_bytes>>>(As);

    reduce_out<<<(N_OUT * 8) / 256, 256>>>(bs, out);
}